// round 11
// baseline (speedup 1.0000x reference)
#include <cuda_runtime.h>

// Problem constants
constexpr int B_  = 1024;   // batch
constexpr int DI_ = 1024;   // input dim
constexpr int H_  = 2048;   // hidden dim
constexpr int O_  = 256;    // output dim
constexpr int T_  = 50;     // time steps
// cuBLAS split-K hypothesis:
//   GEMM1 (64-128 output CTAs on 148 SMs) -> splitK=2 -> K-panels of 512
//   GEMM2 (16 output CTAs)               -> splitK=8 -> K-panels of 256
constexpr int KC1_TILES = 64;   // GEMM1: 512 k-elements per panel (BK=8)
constexpr int KC2_TILES = 16;   // GEMM2: 256 k-elements per panel (BK=16)
#define BETA 0.9f
#define TH   1.0f

// Scratch (device globals; no allocation allowed)
__device__ __align__(16) float g_cur1[B_ * H_];   // 8 MB, fc1 output (constant over t)
__device__ __align__(16) float g_mem1[B_ * H_];   // 8 MB
__device__ __align__(16) float g_spk1[B_ * H_];   // 8 MB
__device__ __align__(16) float g_mem2[B_ * O_];   // 1 MB

// ---------------------------------------------------------------------------
// Init: zero mem1, mem2, and both output accumulators (d_out is poisoned).
// ---------------------------------------------------------------------------
__global__ void init_kernel(float* __restrict__ out) {
    int i = blockIdx.x * blockDim.x + threadIdx.x;
    const int total = B_ * H_ + B_ * O_;
    if (i < total) out[i] = 0.0f;
    if (i < B_ * H_) g_mem1[i] = 0.0f;
    if (i < B_ * O_) g_mem2[i] = 0.0f;
}

// ---------------------------------------------------------------------------
// GEMM1: cur1[b,h] = splitK=2 sum over d of x[b,d]*W1[h,d], + b1[h]
// Each 512-panel: ascending fused-FMA chain into a fresh accumulator.
// Partials combined sequentially (ascending split index); bias last.
// Tiles: BM=64 (b), BN=64 (h), BK=8. 256 threads, 4x4 per thread.
// ---------------------------------------------------------------------------
__global__ void gemm1_kernel(const float* __restrict__ x,
                             const float* __restrict__ W1,
                             const float* __restrict__ b1) {
    __shared__ float As[8][64];
    __shared__ float Bs[8][64];

    const int bm = blockIdx.y * 64;
    const int bn = blockIdx.x * 64;
    const int tid = threadIdx.x;          // 0..255
    const int tx = tid % 16;              // n direction (16 * 4 = 64)
    const int ty = tid / 16;              // m direction (16 * 4 = 64)

    const int lr = tid / 4;               // 0..63 tile row
    const int lc = (tid % 4) * 2;         // 0,2,4,6 (k within tile)

    float tot[4][4] = {};   // running total (sum of completed panels)
    float acc[4][4] = {};   // current panel accumulator (FMA chain)

    const int ntiles = DI_ / 8;           // 128
    for (int t = 0; t < ntiles; t++) {
        int k0 = t * 8;
        float2 av = *(const float2*)&x [(bm + lr) * DI_ + k0 + lc];
        float2 bv = *(const float2*)&W1[(bn + lr) * DI_ + k0 + lc];
        As[lc + 0][lr] = av.x; As[lc + 1][lr] = av.y;
        Bs[lc + 0][lr] = bv.x; Bs[lc + 1][lr] = bv.y;
        __syncthreads();

        #pragma unroll
        for (int k = 0; k < 8; k++) {     // strictly ascending k
            float4 a = *(const float4*)&As[k][ty * 4];
            float4 b = *(const float4*)&Bs[k][tx * 4];
            float ar[4] = {a.x, a.y, a.z, a.w};
            float br[4] = {b.x, b.y, b.z, b.w};
            #pragma unroll
            for (int i = 0; i < 4; i++)
                #pragma unroll
                for (int j = 0; j < 4; j++)
                    acc[i][j] = __fmaf_rn(ar[i], br[j], acc[i][j]);
        }
        __syncthreads();

        if ((t + 1) % KC1_TILES == 0) {   // split boundary (k = 512)
            #pragma unroll
            for (int i = 0; i < 4; i++)
                #pragma unroll
                for (int j = 0; j < 4; j++) {
                    tot[i][j] = __fadd_rn(tot[i][j], acc[i][j]);
                    acc[i][j] = 0.0f;
                }
        }
    }

    #pragma unroll
    for (int i = 0; i < 4; i++) {
        int row = bm + ty * 4 + i;
        #pragma unroll
        for (int j = 0; j < 4; j++) {
            int col = bn + tx * 4 + j;
            float v = __fadd_rn(tot[i][j], acc[i][j]);  // folds are exact 0-adds at end
            g_cur1[row * H_ + col] = __fadd_rn(v, b1[col]);
        }
    }
}

// ---------------------------------------------------------------------------
// Layer-1 LIF step (elementwise over [B, H]), vectorized float4.
// Strict *_rn intrinsics, separate ops (XLA HLO style, no contraction).
// ---------------------------------------------------------------------------
__device__ __forceinline__ float lif1(float m, float c, float& spk) {
    float r = (m > TH) ? TH : 0.0f;
    float t = __fmul_rn(BETA, m);
    t = __fadd_rn(t, c);
    t = __fsub_rn(t, r);
    spk = (t > TH) ? 1.0f : 0.0f;
    return t;
}

__global__ void layer1_kernel(float* __restrict__ hsum) {
    int i = (blockIdx.x * blockDim.x + threadIdx.x) * 4;
    float4 m  = *(float4*)&g_mem1[i];
    float4 c  = *(const float4*)&g_cur1[i];
    float4 hs = *(float4*)&hsum[i];
    float4 s;

    m.x = lif1(m.x, c.x, s.x);
    m.y = lif1(m.y, c.y, s.y);
    m.z = lif1(m.z, c.z, s.z);
    m.w = lif1(m.w, c.w, s.w);
    hs.x = __fadd_rn(hs.x, s.x);
    hs.y = __fadd_rn(hs.y, s.y);
    hs.z = __fadd_rn(hs.z, s.z);
    hs.w = __fadd_rn(hs.w, s.w);

    *(float4*)&g_mem1[i] = m;
    *(float4*)&g_spk1[i] = s;
    *(float4*)&hsum[i]   = hs;
}

// ---------------------------------------------------------------------------
// GEMM2 + layer-2 LIF fused: splitK=8 (panels of 256) sum over h of
// spk1[b,h]*W2[o,h]; partials combined sequentially; + b2; strict f32 LIF.
// Tiles: BM=64 (b), BN=32 (o), BK=16. 128 threads, 4x4 per thread.
// ---------------------------------------------------------------------------
__global__ void gemm2_kernel(const float* __restrict__ W2,
                             const float* __restrict__ b2,
                             float* __restrict__ osum) {
    __shared__ float As[16][64];
    __shared__ float Bs[16][32];

    const int bm = blockIdx.y * 64;       // batch tile
    const int bn = blockIdx.x * 32;       // out tile
    const int tid = threadIdx.x;          // 0..127
    const int tx = tid % 8;               // n direction (8 * 4 = 32)
    const int ty = tid / 8;               // m direction (16 * 4 = 64)

    const int lrA = tid / 2;              // 0..63
    const int lcA = (tid % 2) * 8;        // 0 or 8
    const int lrB = tid / 4;              // 0..31
    const int lcB = (tid % 4) * 4;        // 0,4,8,12

    float tot[4][4] = {};
    float acc[4][4] = {};

    const int ntiles = H_ / 16;           // 128
    for (int t = 0; t < ntiles; t++) {
        int k0 = t * 16;
        float4 a0 = *(const float4*)&g_spk1[(bm + lrA) * H_ + k0 + lcA];
        float4 a1 = *(const float4*)&g_spk1[(bm + lrA) * H_ + k0 + lcA + 4];
        float4 bv = *(const float4*)&W2   [(bn + lrB) * H_ + k0 + lcB];
        As[lcA + 0][lrA] = a0.x; As[lcA + 1][lrA] = a0.y;
        As[lcA + 2][lrA] = a0.z; As[lcA + 3][lrA] = a0.w;
        As[lcA + 4][lrA] = a1.x; As[lcA + 5][lrA] = a1.y;
        As[lcA + 6][lrA] = a1.z; As[lcA + 7][lrA] = a1.w;
        Bs[lcB + 0][lrB] = bv.x; Bs[lcB + 1][lrB] = bv.y;
        Bs[lcB + 2][lrB] = bv.z; Bs[lcB + 3][lrB] = bv.w;
        __syncthreads();

        #pragma unroll
        for (int k = 0; k < 16; k++) {    // strictly ascending k
            float4 a = *(const float4*)&As[k][ty * 4];
            float4 b = *(const float4*)&Bs[k][tx * 4];
            float ar[4] = {a.x, a.y, a.z, a.w};
            float br[4] = {b.x, b.y, b.z, b.w};
            #pragma unroll
            for (int i = 0; i < 4; i++)
                #pragma unroll
                for (int j = 0; j < 4; j++)
                    acc[i][j] = __fmaf_rn(ar[i], br[j], acc[i][j]);
        }
        __syncthreads();

        if ((t + 1) % KC2_TILES == 0) {   // split boundary (k multiple of 256)
            #pragma unroll
            for (int i = 0; i < 4; i++)
                #pragma unroll
                for (int j = 0; j < 4; j++) {
                    tot[i][j] = __fadd_rn(tot[i][j], acc[i][j]);
                    acc[i][j] = 0.0f;
                }
        }
    }

    // Fused layer-2 LIF epilogue (strict f32)
    #pragma unroll
    for (int i = 0; i < 4; i++) {
        int b = bm + ty * 4 + i;
        #pragma unroll
        for (int j = 0; j < 4; j++) {
            int o   = bn + tx * 4 + j;
            int idx = b * O_ + o;
            float v   = __fadd_rn(tot[i][j], acc[i][j]);  // exact 0-add at end
            float cur = __fadd_rn(v, b2[o]);
            float m2  = g_mem2[idx];
            float r   = (m2 > TH) ? TH : 0.0f;
            float tt  = __fmul_rn(BETA, m2);
            tt = __fadd_rn(tt, cur);
            tt = __fsub_rn(tt, r);
            float s = (tt > TH) ? 1.0f : 0.0f;
            g_mem2[idx] = tt;
            osum[idx] = __fadd_rn(osum[idx], s);
        }
    }
}

// ---------------------------------------------------------------------------
// Launch
// ---------------------------------------------------------------------------
extern "C" void kernel_launch(void* const* d_in, const int* in_sizes, int n_in,
                              void* d_out, int out_size) {
    const float* x  = (const float*)d_in[0];   // [1024, 1024]
    const float* W1 = (const float*)d_in[1];   // [2048, 1024]
    const float* b1 = (const float*)d_in[2];   // [2048]
    const float* W2 = (const float*)d_in[3];   // [256, 2048]
    const float* b2 = (const float*)d_in[4];   // [256]
    float* out   = (float*)d_out;              // h_sum [1024*2048] ++ out_sum [1024*256]
    float* hsum  = out;
    float* osum  = out + B_ * H_;

    // 1. Init accumulators / state
    {
        int total = B_ * H_ + B_ * O_;
        init_kernel<<<(total + 255) / 256, 256>>>(out);
    }

    // 2. Hoisted fc1: cur1 = x @ W1^T + b1  (splitK=2 order)
    {
        dim3 grid(H_ / 64, B_ / 64);   // (32, 16)
        gemm1_kernel<<<grid, 256>>>(x, W1, b1);
    }

    // 3. Time loop: 50 x (layer1 LIF, fused GEMM2 splitK=8 + layer2 LIF)
    for (int t = 0; t < T_; t++) {
        layer1_kernel<<<(B_ * H_ / 4) / 256, 256>>>(hsum);
        dim3 grid2(O_ / 32, B_ / 64);  // (8, 16)
        gemm2_kernel<<<grid2, 128>>>(W2, b2, osum);
    }
}

// round 12
// speedup vs baseline: 1.4288x; 1.4288x over previous
#include <cuda_runtime.h>

// Problem constants
constexpr int B_  = 1024;   // batch
constexpr int DI_ = 1024;   // input dim
constexpr int H_  = 2048;   // hidden dim
constexpr int O_  = 256;    // output dim
constexpr int T_  = 50;     // time steps
// cuBLAS split-K numerics (VALIDATED in R11 — do not change):
//   GEMM1: splitK=2 -> K-panels of 512 ; GEMM2: splitK=8 -> K-panels of 256
constexpr int KC1_TILES = 64;   // GEMM1: 512 k per panel (BK=8)
#define BETA 0.9f
#define TH   1.0f

// Scratch (device globals; no allocation allowed)
__device__ __align__(16) float g_cur1[B_ * H_];   // 8 MB, fc1 output (constant over t)
__device__ __align__(16) float g_mem1[B_ * H_];   // 8 MB
__device__ __align__(16) float g_spk1[B_ * H_];   // 8 MB
__device__ __align__(16) float g_mem2[B_ * O_];   // 1 MB

// ---------------------------------------------------------------------------
// Packed f32x2 helpers (Blackwell). Each lane is an independent IEEE-rn op,
// so fma2/add2 are BIT-IDENTICAL to two scalar __fmaf_rn/__fadd_rn.
// ---------------------------------------------------------------------------
__device__ __forceinline__ void fma2(unsigned long long& d,
                                     unsigned long long a,
                                     unsigned long long b) {
    asm("fma.rn.f32x2 %0, %1, %2, %0;" : "+l"(d) : "l"(a), "l"(b));
}
__device__ __forceinline__ void add2(unsigned long long& d, unsigned long long a) {
    asm("add.rn.f32x2 %0, %0, %1;" : "+l"(d) : "l"(a));
}
__device__ __forceinline__ unsigned long long pack2(float x, float y) {
    unsigned long long r;
    asm("mov.b64 %0, {%1, %2};" : "=l"(r) : "f"(x), "f"(y));
    return r;
}
__device__ __forceinline__ float2 unpack2(unsigned long long v) {
    float2 r;
    asm("mov.b64 {%0, %1}, %2;" : "=f"(r.x), "=f"(r.y) : "l"(v));
    return r;
}

// ---------------------------------------------------------------------------
// Init: zero mem1, mem2, and both output accumulators (d_out is poisoned).
// ---------------------------------------------------------------------------
__global__ void init_kernel(float* __restrict__ out) {
    int i = blockIdx.x * blockDim.x + threadIdx.x;
    const int total = B_ * H_ + B_ * O_;
    if (i < total) out[i] = 0.0f;
    if (i < B_ * H_) g_mem1[i] = 0.0f;
    if (i < B_ * O_) g_mem2[i] = 0.0f;
}

// ---------------------------------------------------------------------------
// GEMM1 (UNCHANGED from R11 — produces bit-exact spk1 trajectory):
// splitK=2: ascending FMA chain, fold at k=512, bias last.
// ---------------------------------------------------------------------------
__global__ void gemm1_kernel(const float* __restrict__ x,
                             const float* __restrict__ W1,
                             const float* __restrict__ b1) {
    __shared__ float As[8][64];
    __shared__ float Bs[8][64];

    const int bm = blockIdx.y * 64;
    const int bn = blockIdx.x * 64;
    const int tid = threadIdx.x;          // 0..255
    const int tx = tid % 16;
    const int ty = tid / 16;

    const int lr = tid / 4;
    const int lc = (tid % 4) * 2;

    float tot[4][4] = {};
    float acc[4][4] = {};

    const int ntiles = DI_ / 8;           // 128
    for (int t = 0; t < ntiles; t++) {
        int k0 = t * 8;
        float2 av = *(const float2*)&x [(bm + lr) * DI_ + k0 + lc];
        float2 bv = *(const float2*)&W1[(bn + lr) * DI_ + k0 + lc];
        As[lc + 0][lr] = av.x; As[lc + 1][lr] = av.y;
        Bs[lc + 0][lr] = bv.x; Bs[lc + 1][lr] = bv.y;
        __syncthreads();

        #pragma unroll
        for (int k = 0; k < 8; k++) {
            float4 a = *(const float4*)&As[k][ty * 4];
            float4 b = *(const float4*)&Bs[k][tx * 4];
            float ar[4] = {a.x, a.y, a.z, a.w};
            float br[4] = {b.x, b.y, b.z, b.w};
            #pragma unroll
            for (int i = 0; i < 4; i++)
                #pragma unroll
                for (int j = 0; j < 4; j++)
                    acc[i][j] = __fmaf_rn(ar[i], br[j], acc[i][j]);
        }
        __syncthreads();

        if ((t + 1) % KC1_TILES == 0) {
            #pragma unroll
            for (int i = 0; i < 4; i++)
                #pragma unroll
                for (int j = 0; j < 4; j++) {
                    tot[i][j] = __fadd_rn(tot[i][j], acc[i][j]);
                    acc[i][j] = 0.0f;
                }
        }
    }

    #pragma unroll
    for (int i = 0; i < 4; i++) {
        int row = bm + ty * 4 + i;
        #pragma unroll
        for (int j = 0; j < 4; j++) {
            int col = bn + tx * 4 + j;
            float v = __fadd_rn(tot[i][j], acc[i][j]);
            g_cur1[row * H_ + col] = __fadd_rn(v, b1[col]);
        }
    }
}

// ---------------------------------------------------------------------------
// Layer-1 LIF (UNCHANGED). Strict *_rn, no contraction.
// ---------------------------------------------------------------------------
__device__ __forceinline__ float lif1(float m, float c, float& spk) {
    float r = (m > TH) ? TH : 0.0f;
    float t = __fmul_rn(BETA, m);
    t = __fadd_rn(t, c);
    t = __fsub_rn(t, r);
    spk = (t > TH) ? 1.0f : 0.0f;
    return t;
}

__global__ void layer1_kernel(float* __restrict__ hsum) {
    int i = (blockIdx.x * blockDim.x + threadIdx.x) * 4;
    float4 m  = *(float4*)&g_mem1[i];
    float4 c  = *(const float4*)&g_cur1[i];
    float4 hs = *(float4*)&hsum[i];
    float4 s;

    m.x = lif1(m.x, c.x, s.x);
    m.y = lif1(m.y, c.y, s.y);
    m.z = lif1(m.z, c.z, s.z);
    m.w = lif1(m.w, c.w, s.w);
    hs.x = __fadd_rn(hs.x, s.x);
    hs.y = __fadd_rn(hs.y, s.y);
    hs.z = __fadd_rn(hs.z, s.z);
    hs.w = __fadd_rn(hs.w, s.w);

    *(float4*)&g_mem1[i] = m;
    *(float4*)&g_spk1[i] = s;
    *(float4*)&hsum[i]   = hs;
}

// ---------------------------------------------------------------------------
// GEMM2 v2 + layer-2 LIF fused. Bit-identical numerics to R11:
// per output (b,o): ascending-k rn-FMA chain, fold (rn-add into tot) at every
// k multiple of 256, final v=fadd(tot,0), +b2 rn-add, strict-rn LIF.
// NEW: BM=32/BN=32 grid (8,32)=256 blocks, 128 thr; f32x2 dual-lane FMA
// (per-lane IEEE-rn == scalar); double-buffered smem, 1 bar/tile.
// Thread: 2 m-rows x 4 n-cols; acc packed over n-pairs -> 4 x u64.
// ---------------------------------------------------------------------------
__global__ void gemm2_kernel(const float* __restrict__ W2,
                             const float* __restrict__ b2,
                             float* __restrict__ osum) {
    // stride 34 floats: 8B-aligned rows (even), conflict-free stores
    __shared__ float As[2][16][34];   // [stage][k][m]  (spk1 tile)
    __shared__ float Bs[2][16][34];   // [stage][k][n]  (W2 tile)

    const int bm = blockIdx.y * 32;       // batch tile
    const int bn = blockIdx.x * 32;       // out tile
    const int tid = threadIdx.x;          // 0..127
    const int tx = tid % 8;               // n-group: 4 n each
    const int ty = tid / 8;               // m-group: 2 m each (0..15)

    // loaders: 32 rows x 16 k per tile; 128 thr x float4
    const int lr = tid / 4;               // 0..31 row (m or n)
    const int lc = (tid % 4) * 4;         // k offset 0,4,8,12

    const float* aSrc = &g_spk1[(bm + lr) * H_ + lc];
    const float* bSrc = &W2    [(bn + lr) * H_ + lc];

    unsigned long long acc[2][2];         // [m][n-pair]
    unsigned long long tot[2][2];
    #pragma unroll
    for (int i = 0; i < 2; i++)
        #pragma unroll
        for (int p = 0; p < 2; p++) { acc[i][p] = 0ull; tot[i][p] = 0ull; }

    const int NT = H_ / 16;               // 128 tiles

    // preload tile 0
    float4 pa = *(const float4*)(aSrc);
    float4 pb = *(const float4*)(bSrc);
    {
        As[0][lc + 0][lr] = pa.x; As[0][lc + 1][lr] = pa.y;
        As[0][lc + 2][lr] = pa.z; As[0][lc + 3][lr] = pa.w;
        Bs[0][lc + 0][lr] = pb.x; Bs[0][lc + 1][lr] = pb.y;
        Bs[0][lc + 2][lr] = pb.z; Bs[0][lc + 3][lr] = pb.w;
    }
    __syncthreads();

    for (int t = 0; t < NT; t++) {
        const int st = t & 1;
        // issue next tile's global loads early (hidden by compute)
        if (t + 1 < NT) {
            pa = *(const float4*)(aSrc + (t + 1) * 16);
            pb = *(const float4*)(bSrc + (t + 1) * 16);
        }

        #pragma unroll
        for (int k = 0; k < 16; k++) {    // strictly ascending k
            float2 av = *(const float2*)&As[st][k][ty * 2];
            unsigned long long b01 =
                *(const unsigned long long*)&Bs[st][k][tx * 4];
            unsigned long long b23 =
                *(const unsigned long long*)&Bs[st][k][tx * 4 + 2];
            unsigned long long aa0 = pack2(av.x, av.x);
            unsigned long long aa1 = pack2(av.y, av.y);
            fma2(acc[0][0], aa0, b01);
            fma2(acc[0][1], aa0, b23);
            fma2(acc[1][0], aa1, b01);
            fma2(acc[1][1], aa1, b23);
        }

        if (((t + 1) & 15) == 0) {        // fold at k multiple of 256
            #pragma unroll
            for (int i = 0; i < 2; i++)
                #pragma unroll
                for (int p = 0; p < 2; p++) {
                    add2(tot[i][p], acc[i][p]);   // per-lane rn add
                    acc[i][p] = 0ull;
                }
        }

        if (t + 1 < NT) {
            const int ns = (t + 1) & 1;
            As[ns][lc + 0][lr] = pa.x; As[ns][lc + 1][lr] = pa.y;
            As[ns][lc + 2][lr] = pa.z; As[ns][lc + 3][lr] = pa.w;
            Bs[ns][lc + 0][lr] = pb.x; Bs[ns][lc + 1][lr] = pb.y;
            Bs[ns][lc + 2][lr] = pb.z; Bs[ns][lc + 3][lr] = pb.w;
        }
        __syncthreads();
    }

    // Fused layer-2 LIF epilogue (strict f32; identical to R11)
    #pragma unroll
    for (int i = 0; i < 2; i++) {
        int b = bm + ty * 2 + i;
        #pragma unroll
        for (int p = 0; p < 2; p++) {
            float2 tv = unpack2(tot[i][p]);
            float2 av = unpack2(acc[i][p]);   // zeros (exact 0-add, as R11)
            float vs[2] = { __fadd_rn(tv.x, av.x), __fadd_rn(tv.y, av.y) };
            #pragma unroll
            for (int q = 0; q < 2; q++) {
                int o   = bn + tx * 4 + p * 2 + q;
                int idx = b * O_ + o;
                float cur = __fadd_rn(vs[q], b2[o]);
                float m2  = g_mem2[idx];
                float r   = (m2 > TH) ? TH : 0.0f;
                float tt  = __fmul_rn(BETA, m2);
                tt = __fadd_rn(tt, cur);
                tt = __fsub_rn(tt, r);
                float s = (tt > TH) ? 1.0f : 0.0f;
                g_mem2[idx] = tt;
                osum[idx] = __fadd_rn(osum[idx], s);
            }
        }
    }
}

// ---------------------------------------------------------------------------
// Launch
// ---------------------------------------------------------------------------
extern "C" void kernel_launch(void* const* d_in, const int* in_sizes, int n_in,
                              void* d_out, int out_size) {
    const float* x  = (const float*)d_in[0];   // [1024, 1024]
    const float* W1 = (const float*)d_in[1];   // [2048, 1024]
    const float* b1 = (const float*)d_in[2];   // [2048]
    const float* W2 = (const float*)d_in[3];   // [256, 2048]
    const float* b2 = (const float*)d_in[4];   // [256]
    float* out   = (float*)d_out;              // h_sum [1024*2048] ++ out_sum [1024*256]
    float* hsum  = out;
    float* osum  = out + B_ * H_;

    // 1. Init accumulators / state
    {
        int total = B_ * H_ + B_ * O_;
        init_kernel<<<(total + 255) / 256, 256>>>(out);
    }

    // 2. Hoisted fc1: cur1 = x @ W1^T + b1  (splitK=2 order)
    {
        dim3 grid(H_ / 64, B_ / 64);   // (32, 16)
        gemm1_kernel<<<grid, 256>>>(x, W1, b1);
    }

    // 3. Time loop: 50 x (layer1 LIF, fused GEMM2 + layer2 LIF)
    for (int t = 0; t < T_; t++) {
        layer1_kernel<<<(B_ * H_ / 4) / 256, 256>>>(hsum);
        dim3 grid2(O_ / 32, B_ / 32);  // (8, 32) = 256 blocks
        gemm2_kernel<<<grid2, 128>>>(W2, b2, osum);
    }
}

// round 15
// speedup vs baseline: 1.4508x; 1.0154x over previous
#include <cuda_runtime.h>

// Problem constants
constexpr int B_  = 1024;   // batch
constexpr int DI_ = 1024;   // input dim
constexpr int H_  = 2048;   // hidden dim
constexpr int O_  = 256;    // output dim
constexpr int T_  = 50;     // time steps
constexpr int KC1_TILES = 64;   // GEMM1: splitK=2 -> fold at k=512 (BK=8)
#define BETA 0.9f
#define TH   1.0f

// Scratch (device globals; no allocation allowed)
__device__ __align__(16) float g_cur1[B_ * H_];   // 8 MB
__device__ __align__(16) float g_mem1[B_ * H_];   // 8 MB
__device__ __align__(16) float g_spk1[B_ * H_];   // 8 MB
__device__ __align__(16) float g_mem2[B_ * O_];   // 1 MB
__device__ __align__(16) float g_w2t [H_ * O_];   // 2 MB, W2 transposed [h][o]
__device__ __align__(16) float g_part[8 * B_ * O_]; // 8 MB, per-panel partials

// ---------------------------------------------------------------------------
// Packed f32x2 FMA (per-lane IEEE-rn == two scalar __fmaf_rn) — validated R12.
// ---------------------------------------------------------------------------
__device__ __forceinline__ void fma2(unsigned long long& d,
                                     unsigned long long a,
                                     unsigned long long b) {
    asm("fma.rn.f32x2 %0, %1, %2, %0;" : "+l"(d) : "l"(a), "l"(b));
}
__device__ __forceinline__ unsigned long long dup2(float x) {
    unsigned long long r;
    asm("mov.b64 %0, {%1, %1};" : "=l"(r) : "f"(x));
    return r;
}
__device__ __forceinline__ float2 unpack2(unsigned long long v) {
    float2 r;
    asm("mov.b64 {%0, %1}, %2;" : "=f"(r.x), "=f"(r.y) : "l"(v));
    return r;
}

// ---------------------------------------------------------------------------
// Init: zero mem1, mem2, and both output accumulators (d_out is poisoned).
// ---------------------------------------------------------------------------
__global__ void init_kernel(float* __restrict__ out) {
    int i = blockIdx.x * blockDim.x + threadIdx.x;
    const int total = B_ * H_ + B_ * O_;
    if (i < total) out[i] = 0.0f;
    if (i < B_ * H_) g_mem1[i] = 0.0f;
    if (i < B_ * O_) g_mem2[i] = 0.0f;
}

// ---------------------------------------------------------------------------
// W2 transpose (once): g_w2t[h][o] = W2[o][h]. Tiled, conflict-free.
// ---------------------------------------------------------------------------
__global__ void w2t_kernel(const float* __restrict__ W2) {
    __shared__ float tile[32][33];
    const int o0 = blockIdx.x * 32;
    const int h0 = blockIdx.y * 32;
    const int tx = threadIdx.x;           // 0..31
    const int ty = threadIdx.y;           // 0..7
    #pragma unroll
    for (int j = 0; j < 4; j++)
        tile[ty + j * 8][tx] = W2[(o0 + ty + j * 8) * H_ + h0 + tx];
    __syncthreads();
    #pragma unroll
    for (int j = 0; j < 4; j++)
        g_w2t[(h0 + ty + j * 8) * O_ + o0 + tx] = tile[tx][ty + j * 8];
}

// ---------------------------------------------------------------------------
// GEMM1 (UNCHANGED, validated: splitK=2, fold at 512, bias last).
// ---------------------------------------------------------------------------
__global__ void gemm1_kernel(const float* __restrict__ x,
                             const float* __restrict__ W1,
                             const float* __restrict__ b1) {
    __shared__ float As[8][64];
    __shared__ float Bs[8][64];

    const int bm = blockIdx.y * 64;
    const int bn = blockIdx.x * 64;
    const int tid = threadIdx.x;
    const int tx = tid % 16;
    const int ty = tid / 16;
    const int lr = tid / 4;
    const int lc = (tid % 4) * 2;

    float tot[4][4] = {};
    float acc[4][4] = {};

    const int ntiles = DI_ / 8;
    for (int t = 0; t < ntiles; t++) {
        int k0 = t * 8;
        float2 av = *(const float2*)&x [(bm + lr) * DI_ + k0 + lc];
        float2 bv = *(const float2*)&W1[(bn + lr) * DI_ + k0 + lc];
        As[lc + 0][lr] = av.x; As[lc + 1][lr] = av.y;
        Bs[lc + 0][lr] = bv.x; Bs[lc + 1][lr] = bv.y;
        __syncthreads();

        #pragma unroll
        for (int k = 0; k < 8; k++) {
            float4 a = *(const float4*)&As[k][ty * 4];
            float4 b = *(const float4*)&Bs[k][tx * 4];
            float ar[4] = {a.x, a.y, a.z, a.w};
            float br[4] = {b.x, b.y, b.z, b.w};
            #pragma unroll
            for (int i = 0; i < 4; i++)
                #pragma unroll
                for (int j = 0; j < 4; j++)
                    acc[i][j] = __fmaf_rn(ar[i], br[j], acc[i][j]);
        }
        __syncthreads();

        if ((t + 1) % KC1_TILES == 0) {
            #pragma unroll
            for (int i = 0; i < 4; i++)
                #pragma unroll
                for (int j = 0; j < 4; j++) {
                    tot[i][j] = __fadd_rn(tot[i][j], acc[i][j]);
                    acc[i][j] = 0.0f;
                }
        }
    }

    #pragma unroll
    for (int i = 0; i < 4; i++) {
        int row = bm + ty * 4 + i;
        #pragma unroll
        for (int j = 0; j < 4; j++) {
            int col = bn + tx * 4 + j;
            float v = __fadd_rn(tot[i][j], acc[i][j]);
            g_cur1[row * H_ + col] = __fadd_rn(v, b1[col]);
        }
    }
}

// ---------------------------------------------------------------------------
// Layer-1 LIF (UNCHANGED, strict *_rn).
// ---------------------------------------------------------------------------
__device__ __forceinline__ float lif1(float m, float c, float& spk) {
    float r = (m > TH) ? TH : 0.0f;
    float t = __fmul_rn(BETA, m);
    t = __fadd_rn(t, c);
    t = __fsub_rn(t, r);
    spk = (t > TH) ? 1.0f : 0.0f;
    return t;
}

__global__ void layer1_kernel(float* __restrict__ hsum) {
    int i = (blockIdx.x * blockDim.x + threadIdx.x) * 4;
    float4 m  = *(float4*)&g_mem1[i];
    float4 c  = *(const float4*)&g_cur1[i];
    float4 hs = *(float4*)&hsum[i];
    float4 s;

    m.x = lif1(m.x, c.x, s.x);
    m.y = lif1(m.y, c.y, s.y);
    m.z = lif1(m.z, c.z, s.z);
    m.w = lif1(m.w, c.w, s.w);
    hs.x = __fadd_rn(hs.x, s.x);
    hs.y = __fadd_rn(hs.y, s.y);
    hs.z = __fadd_rn(hs.z, s.z);
    hs.w = __fadd_rn(hs.w, s.w);

    *(float4*)&g_mem1[i] = m;
    *(float4*)&g_spk1[i] = s;
    *(float4*)&hsum[i]   = hs;
}

// ---------------------------------------------------------------------------
// GEMM2 panel-partial kernel. grid (8, 32, 8): x=o-tile, y=b-tile, z=panel.
// Each block: one 256-k panel, single ascending rn-FMA chain (f32x2 n-pairs,
// bit-identical to scalar). Writes part[z][b][o]. No folds inside.
// Consumer inner loop: 2x LDS.128 + 4x fma2 per k.
// ---------------------------------------------------------------------------
__global__ void gemm2_part_kernel() {
    __shared__ unsigned long long As2[2][16][34];  // m-duplicated spk1 tile
    __shared__ float              Bs [2][16][36];  // W2T tile [k][o]

    const int z  = blockIdx.z;            // panel 0..7
    const int bm = blockIdx.y * 32;
    const int bn = blockIdx.x * 32;
    const int tid = threadIdx.x;          // 0..127
    const int tx = tid % 8;               // 4 n each
    const int ty = tid / 8;               // 2 m each (0..15)
    const int k0 = z * 256;

    // A loader: 32 rows x 16 k; thread -> row lrA, k-offset lcA (float4)
    const int lrA = tid / 4;              // 0..31
    const int lcA = (tid % 4) * 4;        // 0,4,8,12
    const float* aSrc = &g_spk1[(bm + lrA) * H_ + k0 + lcA];
    // B loader: 16 k-rows x 32 o; thread -> k-row kB, o-group og (float4)
    const int kB = tid / 8;               // 0..15
    const int og = tid % 8;               // 0..7
    const float* bSrc = &g_w2t[(k0 + kB) * O_ + bn + og * 4];

    unsigned long long acc[2][2] = {{0ull, 0ull}, {0ull, 0ull}};  // [m][npair]

    // preload tile 0
    float4 pa = *(const float4*)(aSrc);
    float4 pb = *(const float4*)(bSrc);
    {
        As2[0][lcA + 0][lrA] = dup2(pa.x);
        As2[0][lcA + 1][lrA] = dup2(pa.y);
        As2[0][lcA + 2][lrA] = dup2(pa.z);
        As2[0][lcA + 3][lrA] = dup2(pa.w);
        *(float4*)&Bs[0][kB][og * 4] = pb;
    }
    __syncthreads();

    const int NT = 16;                    // 256 k / 16
    for (int t = 0; t < NT; t++) {
        const int st = t & 1;
        if (t + 1 < NT) {
            pa = *(const float4*)(aSrc + (t + 1) * 16);
            pb = *(const float4*)(bSrc + (t + 1) * 16 * O_);
        }

        #pragma unroll
        for (int k = 0; k < 16; k++) {    // strictly ascending k
            ulonglong2 aa = *(const ulonglong2*)&As2[st][k][ty * 2];
            ulonglong2 bb = *(const ulonglong2*)&Bs[st][k][tx * 4];
            fma2(acc[0][0], aa.x, bb.x);
            fma2(acc[0][1], aa.x, bb.y);
            fma2(acc[1][0], aa.y, bb.x);
            fma2(acc[1][1], aa.y, bb.y);
        }

        if (t + 1 < NT) {
            const int ns = (t + 1) & 1;
            As2[ns][lcA + 0][lrA] = dup2(pa.x);
            As2[ns][lcA + 1][lrA] = dup2(pa.y);
            As2[ns][lcA + 2][lrA] = dup2(pa.z);
            As2[ns][lcA + 3][lrA] = dup2(pa.w);
            *(float4*)&Bs[ns][kB][og * 4] = pb;
        }
        __syncthreads();
    }

    // write partials: part[z][b][o], float4 per (thread, m)
    float* base = &g_part[z * (B_ * O_)];
    #pragma unroll
    for (int i = 0; i < 2; i++) {
        int b = bm + ty * 2 + i;
        float2 v0 = unpack2(acc[i][0]);
        float2 v1 = unpack2(acc[i][1]);
        float4 v = make_float4(v0.x, v0.y, v1.x, v1.y);
        *(float4*)&base[b * O_ + bn + tx * 4] = v;
    }
}

// ---------------------------------------------------------------------------
// Combine + layer-2 LIF: sequential rn-fold of the 8 panel partials
// (identical to validated fold order), + bias, strict-rn LIF, out_sum.
// ---------------------------------------------------------------------------
__global__ void combine_kernel(const float* __restrict__ b2,
                               float* __restrict__ osum) {
    int i = blockIdx.x * blockDim.x + threadIdx.x;   // 0..B*O-1
    float tot = g_part[i];                            // rn(0+p0)=p0
    #pragma unroll
    for (int zz = 1; zz < 8; zz++)
        tot = __fadd_rn(tot, g_part[zz * (B_ * O_) + i]);

    int o = i & (O_ - 1);
    float cur = __fadd_rn(tot, b2[o]);
    float m2  = g_mem2[i];
    float r   = (m2 > TH) ? TH : 0.0f;
    float tt  = __fmul_rn(BETA, m2);
    tt = __fadd_rn(tt, cur);
    tt = __fsub_rn(tt, r);
    float s = (tt > TH) ? 1.0f : 0.0f;
    g_mem2[i] = tt;
    osum[i] = __fadd_rn(osum[i], s);
}

// ---------------------------------------------------------------------------
// Launch
// ---------------------------------------------------------------------------
extern "C" void kernel_launch(void* const* d_in, const int* in_sizes, int n_in,
                              void* d_out, int out_size) {
    const float* x  = (const float*)d_in[0];   // [1024, 1024]
    const float* W1 = (const float*)d_in[1];   // [2048, 1024]
    const float* b1 = (const float*)d_in[2];   // [2048]
    const float* W2 = (const float*)d_in[3];   // [256, 2048]
    const float* b2 = (const float*)d_in[4];   // [256]
    float* out   = (float*)d_out;              // h_sum ++ out_sum
    float* hsum  = out;
    float* osum  = out + B_ * H_;

    // 1. Init accumulators / state
    {
        int total = B_ * H_ + B_ * O_;
        init_kernel<<<(total + 255) / 256, 256>>>(out);
    }

    // 2. One-time W2 transpose
    {
        dim3 grid(O_ / 32, H_ / 32);   // (8, 64)
        w2t_kernel<<<grid, dim3(32, 8)>>>(W2);
    }

    // 3. Hoisted fc1: cur1 = x @ W1^T + b1  (splitK=2 order)
    {
        dim3 grid(H_ / 64, B_ / 64);   // (32, 16)
        gemm1_kernel<<<grid, 256>>>(x, W1, b1);
    }

    // 4. Time loop: 50 x (layer1 LIF, gemm2 panel partials, combine+LIF)
    for (int t = 0; t < T_; t++) {
        layer1_kernel<<<(B_ * H_ / 4) / 256, 256>>>(hsum);
        dim3 grid2(O_ / 32, B_ / 32, 8);   // (8, 32, 8) = 2048 blocks
        gemm2_part_kernel<<<grid2, 128>>>();
        combine_kernel<<<(B_ * O_) / 256, 256>>>(b2, osum);
    }
}

// round 17
// speedup vs baseline: 1.5574x; 1.0735x over previous
#include <cuda_runtime.h>

// Problem constants
constexpr int B_  = 1024;   // batch
constexpr int DI_ = 1024;   // input dim
constexpr int H_  = 2048;   // hidden dim
constexpr int O_  = 256;    // output dim
constexpr int T_  = 50;     // time steps
#define BETA 0.9f
#define TH   1.0f

// Scratch (device globals; no allocation allowed)
__device__ __align__(16) float g_cur1[B_ * H_];     // 8 MB
__device__ __align__(16) float g_mem1[B_ * H_];     // 8 MB
__device__ __align__(16) float g_spk1[B_ * H_];     // 8 MB
__device__ __align__(16) float g_mem2[B_ * O_];     // 1 MB
__device__ __align__(16) float g_w2t [H_ * O_];     // 2 MB, W2^T [h][o]
__device__ __align__(16) float g_w1t [DI_ * H_];    // 8 MB, W1^T [d][h]
__device__ __align__(16) float g_part[8 * B_ * O_]; // 8 MB, per-panel partials

// ---------------------------------------------------------------------------
// Packed f32x2 ops (per-lane IEEE-rn == scalar __fmaf_rn/__fadd_rn; validated)
// ---------------------------------------------------------------------------
__device__ __forceinline__ void fma2(unsigned long long& d,
                                     unsigned long long a,
                                     unsigned long long b) {
    asm("fma.rn.f32x2 %0, %1, %2, %0;" : "+l"(d) : "l"(a), "l"(b));
}
__device__ __forceinline__ void add2(unsigned long long& d, unsigned long long a) {
    asm("add.rn.f32x2 %0, %0, %1;" : "+l"(d) : "l"(a));
}
__device__ __forceinline__ unsigned long long dup2(float x) {
    unsigned long long r;
    asm("mov.b64 %0, {%1, %1};" : "=l"(r) : "f"(x));
    return r;
}
__device__ __forceinline__ float2 unpack2(unsigned long long v) {
    float2 r;
    asm("mov.b64 {%0, %1}, %2;" : "=f"(r.x), "=f"(r.y) : "l"(v));
    return r;
}

// ---------------------------------------------------------------------------
// Init: zero mem1, mem2, and both output accumulators (d_out is poisoned).
// ---------------------------------------------------------------------------
__global__ void init_kernel(float* __restrict__ out) {
    int i = blockIdx.x * blockDim.x + threadIdx.x;
    const int total = B_ * H_ + B_ * O_;
    if (i < total) out[i] = 0.0f;
    if (i < B_ * H_) g_mem1[i] = 0.0f;
    if (i < B_ * O_) g_mem2[i] = 0.0f;
}

// ---------------------------------------------------------------------------
// Generic 32x32-tiled transpose: dst[c*R + r] = src[r*C + c]
// ---------------------------------------------------------------------------
__global__ void transpose_kernel(const float* __restrict__ src,
                                 float* __restrict__ dst, int R, int C) {
    __shared__ float tile[32][33];
    const int r0 = blockIdx.x * 32;
    const int c0 = blockIdx.y * 32;
    const int tx = threadIdx.x;           // 0..31
    const int ty = threadIdx.y;           // 0..7
    #pragma unroll
    for (int j = 0; j < 4; j++)
        tile[ty + j * 8][tx] = src[(r0 + ty + j * 8) * C + c0 + tx];
    __syncthreads();
    #pragma unroll
    for (int j = 0; j < 4; j++)
        dst[(c0 + ty + j * 8) * R + r0 + tx] = tile[tx][ty + j * 8];
}

// ---------------------------------------------------------------------------
// GEMM1 v2 (f32x2 engine; BIT-IDENTICAL chains to validated R11 gemm1):
// per output (b,h): ascending-k rn-FMA chain, fold (rn-add) at k=512,
// final v=rn(tot+acc[=0]), bias rn-add. BM=64 (b), BN=64 (h), BK=16,
// 128 threads, 4m x 8n per thread, double-buffered smem.
// ---------------------------------------------------------------------------
__global__ void gemm1_kernel(const float* __restrict__ x,
                             const float* __restrict__ b1) {
    __shared__ unsigned long long As2[2][16][66];  // m-duplicated x tile
    __shared__ float              Bs [2][16][68];  // W1T tile [k][h]

    const int bm = blockIdx.y * 64;
    const int bn = blockIdx.x * 64;
    const int tid = threadIdx.x;          // 0..127
    const int tx = tid % 8;               // 8 h each
    const int ty = tid / 8;               // 4 m each (0..15)

    const int lrA = tid / 2;              // 0..63 m-row
    const int lcA = (tid % 2) * 8;        // k offset 0 or 8
    const float* aSrc = &x[(bm + lrA) * DI_ + lcA];
    const int kB = tid / 8;               // 0..15
    const int og = tid % 8;               // 0..7
    const float* bSrc = &g_w1t[kB * H_ + bn + og * 8];

    unsigned long long acc[4][4], tot[4][4];
    #pragma unroll
    for (int i = 0; i < 4; i++)
        #pragma unroll
        for (int p = 0; p < 4; p++) { acc[i][p] = 0ull; tot[i][p] = 0ull; }

    const int NT = DI_ / 16;              // 64 tiles

    float4 pa0 = *(const float4*)(aSrc);
    float4 pa1 = *(const float4*)(aSrc + 4);
    float4 pb0 = *(const float4*)(bSrc);
    float4 pb1 = *(const float4*)(bSrc + 4);
    {
        As2[0][lcA + 0][lrA] = dup2(pa0.x); As2[0][lcA + 1][lrA] = dup2(pa0.y);
        As2[0][lcA + 2][lrA] = dup2(pa0.z); As2[0][lcA + 3][lrA] = dup2(pa0.w);
        As2[0][lcA + 4][lrA] = dup2(pa1.x); As2[0][lcA + 5][lrA] = dup2(pa1.y);
        As2[0][lcA + 6][lrA] = dup2(pa1.z); As2[0][lcA + 7][lrA] = dup2(pa1.w);
        *(float4*)&Bs[0][kB][og * 8]     = pb0;
        *(float4*)&Bs[0][kB][og * 8 + 4] = pb1;
    }
    __syncthreads();

    for (int t = 0; t < NT; t++) {
        const int st = t & 1;
        if (t + 1 < NT) {
            pa0 = *(const float4*)(aSrc + (t + 1) * 16);
            pa1 = *(const float4*)(aSrc + (t + 1) * 16 + 4);
            pb0 = *(const float4*)(bSrc + (t + 1) * 16 * H_);
            pb1 = *(const float4*)(bSrc + (t + 1) * 16 * H_ + 4);
        }

        #pragma unroll
        for (int k = 0; k < 16; k++) {    // strictly ascending k
            ulonglong2 a01 = *(const ulonglong2*)&As2[st][k][ty * 4];
            ulonglong2 a23 = *(const ulonglong2*)&As2[st][k][ty * 4 + 2];
            ulonglong2 b01 = *(const ulonglong2*)&Bs[st][k][tx * 8];
            ulonglong2 b23 = *(const ulonglong2*)&Bs[st][k][tx * 8 + 4];
            unsigned long long av[4] = {a01.x, a01.y, a23.x, a23.y};
            unsigned long long bv[4] = {b01.x, b01.y, b23.x, b23.y};
            #pragma unroll
            for (int i = 0; i < 4; i++)
                #pragma unroll
                for (int p = 0; p < 4; p++)
                    fma2(acc[i][p], av[i], bv[p]);
        }

        if (((t + 1) & 31) == 0) {        // fold at k = 512, 1024
            #pragma unroll
            for (int i = 0; i < 4; i++)
                #pragma unroll
                for (int p = 0; p < 4; p++) {
                    add2(tot[i][p], acc[i][p]);
                    acc[i][p] = 0ull;
                }
        }

        if (t + 1 < NT) {
            const int ns = (t + 1) & 1;
            As2[ns][lcA + 0][lrA] = dup2(pa0.x); As2[ns][lcA + 1][lrA] = dup2(pa0.y);
            As2[ns][lcA + 2][lrA] = dup2(pa0.z); As2[ns][lcA + 3][lrA] = dup2(pa0.w);
            As2[ns][lcA + 4][lrA] = dup2(pa1.x); As2[ns][lcA + 5][lrA] = dup2(pa1.y);
            As2[ns][lcA + 6][lrA] = dup2(pa1.z); As2[ns][lcA + 7][lrA] = dup2(pa1.w);
            *(float4*)&Bs[ns][kB][og * 8]     = pb0;
            *(float4*)&Bs[ns][kB][og * 8 + 4] = pb1;
        }
        __syncthreads();
    }

    // epilogue: v = tot (acc folded to 0), + bias (rn), store cur1
    #pragma unroll
    for (int i = 0; i < 4; i++) {
        int row = bm + ty * 4 + i;
        #pragma unroll
        for (int p = 0; p < 4; p++) {
            float2 v = unpack2(tot[i][p]);
            int col = bn + tx * 8 + p * 2;
            g_cur1[row * H_ + col]     = __fadd_rn(v.x, b1[col]);
            g_cur1[row * H_ + col + 1] = __fadd_rn(v.y, b1[col + 1]);
        }
    }
}

// ---------------------------------------------------------------------------
// Layer-1 LIF body (strict *_rn, validated) + standalone kernel (t=0).
// ---------------------------------------------------------------------------
__device__ __forceinline__ float lif1(float m, float c, float& spk) {
    float r = (m > TH) ? TH : 0.0f;
    float t = __fmul_rn(BETA, m);
    t = __fadd_rn(t, c);
    t = __fsub_rn(t, r);
    spk = (t > TH) ? 1.0f : 0.0f;
    return t;
}

__device__ __forceinline__ void layer1_body(int i, float* __restrict__ hsum) {
    float4 m  = *(float4*)&g_mem1[i];
    float4 c  = *(const float4*)&g_cur1[i];
    float4 hs = *(float4*)&hsum[i];
    float4 s;
    m.x = lif1(m.x, c.x, s.x);
    m.y = lif1(m.y, c.y, s.y);
    m.z = lif1(m.z, c.z, s.z);
    m.w = lif1(m.w, c.w, s.w);
    hs.x = __fadd_rn(hs.x, s.x);
    hs.y = __fadd_rn(hs.y, s.y);
    hs.z = __fadd_rn(hs.z, s.z);
    hs.w = __fadd_rn(hs.w, s.w);
    *(float4*)&g_mem1[i] = m;
    *(float4*)&g_spk1[i] = s;
    *(float4*)&hsum[i]   = hs;
}

__global__ void layer1_kernel(float* __restrict__ hsum) {
    int i = (blockIdx.x * blockDim.x + threadIdx.x) * 4;
    layer1_body(i, hsum);
}

// ---------------------------------------------------------------------------
// Combine body (sequential rn-fold of 8 panel partials + bias + strict LIF).
// ---------------------------------------------------------------------------
__device__ __forceinline__ void combine_body(int i, const float* __restrict__ b2,
                                             float* __restrict__ osum) {
    float tot = g_part[i];                            // rn(0+p0)=p0
    #pragma unroll
    for (int zz = 1; zz < 8; zz++)
        tot = __fadd_rn(tot, g_part[zz * (B_ * O_) + i]);
    int o = i & (O_ - 1);
    float cur = __fadd_rn(tot, b2[o]);
    float m2  = g_mem2[i];
    float r   = (m2 > TH) ? TH : 0.0f;
    float tt  = __fmul_rn(BETA, m2);
    tt = __fadd_rn(tt, cur);
    tt = __fsub_rn(tt, r);
    float s = (tt > TH) ? 1.0f : 0.0f;
    g_mem2[i] = tt;
    osum[i] = __fadd_rn(osum[i], s);
}

__global__ void combine_kernel(const float* __restrict__ b2,
                               float* __restrict__ osum) {
    int i = blockIdx.x * blockDim.x + threadIdx.x;
    combine_body(i, b2, osum);
}

// ---------------------------------------------------------------------------
// mid_kernel: combine(t) [blocks 0..1023] + layer1(t+1) [blocks 1024..3071].
// Disjoint data; both follow gemm2_part(t) in stream order, so safe.
// ---------------------------------------------------------------------------
__global__ void mid_kernel(const float* __restrict__ b2,
                           float* __restrict__ hsum,
                           float* __restrict__ osum) {
    if (blockIdx.x < 1024) {
        int i = blockIdx.x * 256 + threadIdx.x;       // B*O = 262144
        combine_body(i, b2, osum);
    } else {
        int i = ((blockIdx.x - 1024) * 256 + threadIdx.x) * 4;  // B*H
        layer1_body(i, hsum);
    }
}

// ---------------------------------------------------------------------------
// GEMM2 panel-partial v3. grid (O/64, B/64, 8) = (4, 16, 8) = 512 blocks.
// One 256-k panel per block-z; single ascending rn-FMA chain per output
// (f32x2 lanes independent => bit-identical to scalar). 4m x 8n per thread.
// ---------------------------------------------------------------------------
__global__ void gemm2_part_kernel() {
    __shared__ unsigned long long As2[2][16][66];  // m-duplicated spk1 tile
    __shared__ float              Bs [2][16][68];  // W2T tile [k][o]

    const int z  = blockIdx.z;            // panel 0..7
    const int bm = blockIdx.y * 64;
    const int bn = blockIdx.x * 64;
    const int tid = threadIdx.x;          // 0..127
    const int tx = tid % 8;               // 8 o each
    const int ty = tid / 8;               // 4 m each (0..15)
    const int k0 = z * 256;

    const int lrA = tid / 2;              // 0..63 m-row
    const int lcA = (tid % 2) * 8;        // k offset 0 or 8
    const float* aSrc = &g_spk1[(bm + lrA) * H_ + k0 + lcA];
    const int kB = tid / 8;               // 0..15
    const int og = tid % 8;               // 0..7
    const float* bSrc = &g_w2t[(k0 + kB) * O_ + bn + og * 8];

    unsigned long long acc[4][4];
    #pragma unroll
    for (int i = 0; i < 4; i++)
        #pragma unroll
        for (int p = 0; p < 4; p++) acc[i][p] = 0ull;

    const int NT = 16;                    // 256 k / 16

    float4 pa0 = *(const float4*)(aSrc);
    float4 pa1 = *(const float4*)(aSrc + 4);
    float4 pb0 = *(const float4*)(bSrc);
    float4 pb1 = *(const float4*)(bSrc + 4);
    {
        As2[0][lcA + 0][lrA] = dup2(pa0.x); As2[0][lcA + 1][lrA] = dup2(pa0.y);
        As2[0][lcA + 2][lrA] = dup2(pa0.z); As2[0][lcA + 3][lrA] = dup2(pa0.w);
        As2[0][lcA + 4][lrA] = dup2(pa1.x); As2[0][lcA + 5][lrA] = dup2(pa1.y);
        As2[0][lcA + 6][lrA] = dup2(pa1.z); As2[0][lcA + 7][lrA] = dup2(pa1.w);
        *(float4*)&Bs[0][kB][og * 8]     = pb0;
        *(float4*)&Bs[0][kB][og * 8 + 4] = pb1;
    }
    __syncthreads();

    for (int t = 0; t < NT; t++) {
        const int st = t & 1;
        if (t + 1 < NT) {
            pa0 = *(const float4*)(aSrc + (t + 1) * 16);
            pa1 = *(const float4*)(aSrc + (t + 1) * 16 + 4);
            pb0 = *(const float4*)(bSrc + (t + 1) * 16 * O_);
            pb1 = *(const float4*)(bSrc + (t + 1) * 16 * O_ + 4);
        }

        #pragma unroll
        for (int k = 0; k < 16; k++) {    // strictly ascending k
            ulonglong2 a01 = *(const ulonglong2*)&As2[st][k][ty * 4];
            ulonglong2 a23 = *(const ulonglong2*)&As2[st][k][ty * 4 + 2];
            ulonglong2 b01 = *(const ulonglong2*)&Bs[st][k][tx * 8];
            ulonglong2 b23 = *(const ulonglong2*)&Bs[st][k][tx * 8 + 4];
            unsigned long long av[4] = {a01.x, a01.y, a23.x, a23.y};
            unsigned long long bv[4] = {b01.x, b01.y, b23.x, b23.y};
            #pragma unroll
            for (int i = 0; i < 4; i++)
                #pragma unroll
                for (int p = 0; p < 4; p++)
                    fma2(acc[i][p], av[i], bv[p]);
        }

        if (t + 1 < NT) {
            const int ns = (t + 1) & 1;
            As2[ns][lcA + 0][lrA] = dup2(pa0.x); As2[ns][lcA + 1][lrA] = dup2(pa0.y);
            As2[ns][lcA + 2][lrA] = dup2(pa0.z); As2[ns][lcA + 3][lrA] = dup2(pa0.w);
            As2[ns][lcA + 4][lrA] = dup2(pa1.x); As2[ns][lcA + 5][lrA] = dup2(pa1.y);
            As2[ns][lcA + 6][lrA] = dup2(pa1.z); As2[ns][lcA + 7][lrA] = dup2(pa1.w);
            *(float4*)&Bs[ns][kB][og * 8]     = pb0;
            *(float4*)&Bs[ns][kB][og * 8 + 4] = pb1;
        }
        __syncthreads();
    }

    // write partials part[z][b][o]: 4 m rows x 8 o (two float4 each)
    float* base = &g_part[z * (B_ * O_)];
    #pragma unroll
    for (int i = 0; i < 4; i++) {
        int b = bm + ty * 4 + i;
        float2 v0 = unpack2(acc[i][0]);
        float2 v1 = unpack2(acc[i][1]);
        float2 v2 = unpack2(acc[i][2]);
        float2 v3 = unpack2(acc[i][3]);
        *(float4*)&base[b * O_ + bn + tx * 8]     = make_float4(v0.x, v0.y, v1.x, v1.y);
        *(float4*)&base[b * O_ + bn + tx * 8 + 4] = make_float4(v2.x, v2.y, v3.x, v3.y);
    }
}

// ---------------------------------------------------------------------------
// Launch
// ---------------------------------------------------------------------------
extern "C" void kernel_launch(void* const* d_in, const int* in_sizes, int n_in,
                              void* d_out, int out_size) {
    const float* x  = (const float*)d_in[0];   // [1024, 1024]
    const float* W1 = (const float*)d_in[1];   // [2048, 1024]
    const float* b1 = (const float*)d_in[2];   // [2048]
    const float* W2 = (const float*)d_in[3];   // [256, 2048]
    const float* b2 = (const float*)d_in[4];   // [256]
    float* out   = (float*)d_out;              // h_sum ++ out_sum
    float* hsum  = out;
    float* osum  = out + B_ * H_;

    // 1. Init accumulators / state
    {
        int total = B_ * H_ + B_ * O_;
        init_kernel<<<(total + 255) / 256, 256>>>(out);
    }

    // 2. One-time transposes: W2 -> w2t [h][o], W1 -> w1t [d][h]
    {
        float* w2t; cudaGetSymbolAddress((void**)&w2t, g_w2t);
        float* w1t; cudaGetSymbolAddress((void**)&w1t, g_w1t);
        transpose_kernel<<<dim3(O_ / 32, H_ / 32), dim3(32, 8)>>>(W2, w2t, O_, H_);
        transpose_kernel<<<dim3(H_ / 32, DI_ / 32), dim3(32, 8)>>>(W1, w1t, H_, DI_);
    }

    // 3. Hoisted fc1: cur1 = x @ W1^T + b1  (splitK=2 chains, f32x2 engine)
    {
        dim3 grid(H_ / 64, B_ / 64);   // (32, 16)
        gemm1_kernel<<<grid, 128>>>(x, b1);
    }

    // 4. Time loop
    layer1_kernel<<<(B_ * H_ / 4) / 256, 256>>>(hsum);          // t = 0
    for (int t = 0; t < T_ - 1; t++) {
        dim3 grid2(O_ / 64, B_ / 64, 8);                        // 512 blocks
        gemm2_part_kernel<<<grid2, 128>>>();
        mid_kernel<<<3072, 256>>>(b2, hsum, osum);              // combine(t)+layer1(t+1)
    }
    {
        dim3 grid2(O_ / 64, B_ / 64, 8);
        gemm2_part_kernel<<<grid2, 128>>>();                    // t = 49
        combine_kernel<<<(B_ * O_) / 256, 256>>>(b2, osum);     // t = 49
    }
}